// round 15
// baseline (speedup 1.0000x reference)
#include <cuda_runtime.h>
#include <cuda_bf16.h>
#include <cuda_fp16.h>
#include <cstdint>

#define M_Q 2048
#define DV  1024
#define NH  16
#define HD  64
#define LOG2E 1.4426950408889634f

// Scratch (device globals: allocation-free)
__device__ float g_q[M_Q * DV];                 // fp32 q (residual for attn)
__device__ float g_attn[M_Q * DV];              // attention output (scrambled, fp32)
__device__ __half g_attnh[M_Q * DV];            // fp16 copy for Wo GEMM
__device__ __nv_bfloat16 g_qh[M_Q * DV];        // bf16 q * log2e (attention only)
__device__ __nv_bfloat16 g_kh[M_Q * DV];
__device__ __nv_bfloat16 g_vh[M_Q * DV];
// fp16 pre-converted GEMM inputs
__device__ __half g_qin[M_Q * DV];
__device__ __half g_kin[M_Q * DV];
__device__ __half g_wqh[DV * DV];
__device__ __half g_wkh[DV * DV];
__device__ __half g_wvh[DV * DV];
__device__ __half g_woh[DV * DV];

__device__ __forceinline__ void mma_f16(float (&d)[4],
                                        const uint32_t (&a)[4],
                                        uint32_t b0, uint32_t b1) {
    asm volatile(
        "mma.sync.aligned.m16n8k16.row.col.f32.f16.f16.f32 "
        "{%0,%1,%2,%3}, {%4,%5,%6,%7}, {%8,%9}, {%0,%1,%2,%3};\n"
        : "+f"(d[0]), "+f"(d[1]), "+f"(d[2]), "+f"(d[3])
        : "r"(a[0]), "r"(a[1]), "r"(a[2]), "r"(a[3]), "r"(b0), "r"(b1));
}

__device__ __forceinline__ void mma_bf16(float (&d)[4],
                                         const uint32_t (&a)[4],
                                         uint32_t b0, uint32_t b1) {
    asm volatile(
        "mma.sync.aligned.m16n8k16.row.col.f32.bf16.bf16.f32 "
        "{%0,%1,%2,%3}, {%4,%5,%6,%7}, {%8,%9}, {%0,%1,%2,%3};\n"
        : "+f"(d[0]), "+f"(d[1]), "+f"(d[2]), "+f"(d[3])
        : "r"(a[0]), "r"(a[1]), "r"(a[2]), "r"(a[3]), "r"(b0), "r"(b1));
}

__device__ __forceinline__ void ldsm4(uint32_t& r0, uint32_t& r1,
                                      uint32_t& r2, uint32_t& r3, uint32_t addr) {
    asm volatile("ldmatrix.sync.aligned.m8n8.x4.shared.b16 {%0,%1,%2,%3}, [%4];\n"
                 : "=r"(r0), "=r"(r1), "=r"(r2), "=r"(r3) : "r"(addr));
}
__device__ __forceinline__ void ldsm4t(uint32_t& r0, uint32_t& r1,
                                       uint32_t& r2, uint32_t& r3, uint32_t addr) {
    asm volatile("ldmatrix.sync.aligned.m8n8.x4.trans.shared.b16 {%0,%1,%2,%3}, [%4];\n"
                 : "=r"(r0), "=r"(r1), "=r"(r2), "=r"(r3) : "r"(addr));
}

__device__ __forceinline__ uint32_t packbf(float lo, float hi) {
    uint32_t r;
    asm("cvt.rn.bf16x2.f32 %0, %1, %2;" : "=r"(r) : "f"(hi), "f"(lo));
    return r;
}

// packed bf16x2 exp2 (sm_90+)
__device__ __forceinline__ uint32_t ex2_bf16x2(uint32_t a) {
    uint32_t r;
    asm("ex2.approx.ftz.bf16x2 %0, %1;" : "=r"(r) : "r"(a));
    return r;
}

// ---------------------------------------------------------------------------
// Pre-convert pass: fp32 -> fp16 copies of Q, K, Wq, Wk, Wv, Wo.
// ---------------------------------------------------------------------------
__global__ __launch_bounds__(256) void conv_f16(
    const float4* __restrict__ Q, const float4* __restrict__ K,
    const float4* __restrict__ Wq, const float4* __restrict__ Wk,
    const float4* __restrict__ Wv, const float4* __restrict__ Wo)
{
    const int i = blockIdx.x * 256 + threadIdx.x;   // 0 .. 2M-1
    const float4* src;
    __half* dst;
    int off;
    if (i < 524288)        { src = Q;  dst = g_qin; off = i; }
    else if (i < 1048576)  { src = K;  dst = g_kin; off = i - 524288; }
    else if (i < 1310720)  { src = Wq; dst = g_wqh; off = i - 1048576; }
    else if (i < 1572864)  { src = Wk; dst = g_wkh; off = i - 1310720; }
    else if (i < 1835008)  { src = Wv; dst = g_wvh; off = i - 1572864; }
    else                   { src = Wo; dst = g_woh; off = i - 1835008; }
    const float4 v = src[off];
    __half2* d2 = reinterpret_cast<__half2*>(dst) + off * 2;
    d2[0] = __floats2half2_rn(v.x, v.y);
    d2[1] = __floats2half2_rn(v.z, v.w);
}

// ---------------------------------------------------------------------------
// GEMM v4 (fp16 tensor cores): C = epilogue(A[2048,1024] @ W[1024,1024]^T + b)
// BM=128 BN=64 BK=64; 128 threads, warps 2(m) x 2(n), warp tile 64x32.
// 3-stage cp.async pipeline (wait_group 1 steady-state); ldmatrix frags.
// 2 CTAs/SM (27.6KB/stage x 3 = 83KB, x2 = 166KB < 228KB).
// mode 0: Cf=fp32 + Ch0=bf16(v*log2e)   (q projection)
// mode 1: N=2048 fused; n<1024 -> W0/b0/Ch0 else W1/b1/Ch1   (k,v projection)
// mode 2: Cf = resid + relu(acc+bias)   (output projection)
// ---------------------------------------------------------------------------
#define LDH 72
#define ASTG (128 * LDH)               // A halves per stage
#define BSTG (64 * LDH)                // B halves per stage
#define STGB ((ASTG + BSTG) * 2)       // bytes per stage
#define G4SMEM (3 * STGB)

__device__ __forceinline__ void gemm4_issue(uint32_t smbase, int stage, int kb,
                                            const __half* __restrict__ A,
                                            const __half* __restrict__ W,
                                            int bm0, int n0, int tid)
{
    const uint32_t base = smbase + stage * STGB;
    // A: 128x64 halves = 1024 16B-chunks; B: 64x64 = 512 chunks; 12/thread
    #pragma unroll
    for (int i = 0; i < 8; i++) {
        const int id = tid + i * 128;          // 0..1023
        const int r  = id >> 3;
        const int ch = (id & 7) << 3;
        const __half* srcA = A + (size_t)(bm0 + r) * DV + kb * 64 + ch;
        asm volatile("cp.async.cg.shared.global [%0], [%1], 16;\n"
                     :: "r"(base + (r * LDH + ch) * 2), "l"(srcA));
    }
    #pragma unroll
    for (int i = 0; i < 4; i++) {
        const int id = tid + i * 128;          // 0..511
        const int r  = id >> 3;
        const int ch = (id & 7) << 3;
        const __half* srcW = W + (size_t)(n0 + r) * DV + kb * 64 + ch;
        asm volatile("cp.async.cg.shared.global [%0], [%1], 16;\n"
                     :: "r"(base + (ASTG + r * LDH + ch) * 2), "l"(srcW));
    }
    asm volatile("cp.async.commit_group;\n");
}

__global__ __launch_bounds__(128, 2) void gemm4(
    const __half* __restrict__ A,
    const __half* __restrict__ W0, const __half* __restrict__ W1,
    const float* __restrict__ b0, const float* __restrict__ b1,
    float* __restrict__ Cf,
    __nv_bfloat16* __restrict__ Ch0, __nv_bfloat16* __restrict__ Ch1,
    const float* __restrict__ resid, int mode)
{
    extern __shared__ __align__(16) __half smh[];
    const uint32_t smbase = (uint32_t)__cvta_generic_to_shared(smh);

    const int tid  = threadIdx.x;
    const int lane = tid & 31;
    const int warp = tid >> 5;         // 0..3
    const int wm = warp >> 1;          // 0..1
    const int wn = warp & 1;           // 0..1
    const int bm0 = blockIdx.y * 128;

    const __half* W = W0;
    const float* bias = b0;
    __nv_bfloat16* Ch = Ch0;
    int ncol0 = blockIdx.x * 64;
    if (mode == 1 && ncol0 >= DV) { W = W1; bias = b1; Ch = Ch1; ncol0 -= DV; }

    float acc[4][4][4];
    #pragma unroll
    for (int mi = 0; mi < 4; mi++)
        #pragma unroll
        for (int ni = 0; ni < 4; ni++)
            #pragma unroll
            for (int e = 0; e < 4; e++) acc[mi][ni][e] = 0.f;

    // prologue: 2 stages in flight
    gemm4_issue(smbase, 0, 0, A, W, bm0, ncol0, tid);
    gemm4_issue(smbase, 1, 1, A, W, bm0, ncol0, tid);

    // ldmatrix lane addressing
    const int arow = lane & 15;
    const int acol = (lane >> 4) << 3;
    const int brow = (lane & 7) + 8 * (lane >> 4);
    const int bcol = ((lane >> 3) & 1) << 3;

    int stage = 0;
    for (int kb = 0; kb < 16; kb++) {
        if (kb < 14) asm volatile("cp.async.wait_group 1;\n");
        else         asm volatile("cp.async.wait_group 0;\n");
        __syncthreads();
        if (kb < 14) {
            const int nst = (stage + 2 >= 3) ? stage - 1 : stage + 2;
            gemm4_issue(smbase, nst, kb + 2, A, W, bm0, ncol0, tid);
        }

        const uint32_t abase = smbase + stage * STGB;
        const uint32_t bbase = abase + ASTG * 2;

        #pragma unroll
        for (int ks = 0; ks < 4; ks++) {
            uint32_t af[4][4];
            #pragma unroll
            for (int mi = 0; mi < 4; mi++) {
                const int r = wm * 64 + mi * 16 + arow;
                ldsm4(af[mi][0], af[mi][1], af[mi][2], af[mi][3],
                      abase + (r * LDH + ks * 16 + acol) * 2);
            }
            #pragma unroll
            for (int p = 0; p < 2; p++) {
                uint32_t r0, r1, r2, r3;
                const int n = wn * 32 + 16 * p + brow;
                ldsm4(r0, r1, r2, r3, bbase + (n * LDH + ks * 16 + bcol) * 2);
                #pragma unroll
                for (int mi = 0; mi < 4; mi++) {
                    mma_f16(acc[mi][2 * p],     af[mi], r0, r1);
                    mma_f16(acc[mi][2 * p + 1], af[mi], r2, r3);
                }
            }
        }
        __syncthreads();
        stage = (stage + 1 >= 3) ? 0 : stage + 1;
    }

    // Epilogue
    #pragma unroll
    for (int mi = 0; mi < 4; mi++) {
        #pragma unroll
        for (int ni = 0; ni < 4; ni++) {
            const int r0 = bm0 + wm * 64 + mi * 16 + (lane >> 2);
            const int c0 = ncol0 + wn * 32 + ni * 8 + ((lane & 3) << 1);
            #pragma unroll
            for (int e = 0; e < 4; e++) {
                const int r = r0 + (e >> 1) * 8;
                const int c = c0 + (e & 1);
                float v = acc[mi][ni][e] + bias[c];
                if (mode == 2) {
                    v = resid[(size_t)r * DV + c] + fmaxf(v, 0.f);
                    Cf[(size_t)r * DV + c] = v;
                } else if (mode == 0) {
                    Cf[(size_t)r * DV + c] = v;
                    Ch[(size_t)r * DV + c] = __float2bfloat16(v * LOG2E);
                } else {
                    Ch[(size_t)r * DV + c] = __float2bfloat16(v);
                }
            }
        }
    }
}

// ---------------------------------------------------------------------------
// Attention v3 (unchanged from R14): 4 warps x 32 q-rows, bf16 MMAs,
// log2-domain scores, packed ex2, ones-MMA row sums. 128 threads, 2 CTAs/SM.
// Output scramble: O_heads[h, i, b] -> out[h*128 + (i>>4)][(i&15)*64 + b]
// ---------------------------------------------------------------------------
#define KSTR 72
#define TBUF (64 * KSTR)
#define ONES_BF16X2 0x3F803F80u

__device__ __forceinline__ void issue_kv_tile(uint32_t smbase, int buf, int kt,
                                              int h, int tid) {
    const size_t gro = (size_t)kt * 64 * DV + (size_t)h * HD;
    #pragma unroll
    for (int i = 0; i < 8; i++) {
        const int c = tid + i * 128;             // 0..1023
        const int r = (c >> 3) & 63;
        const int ch = c & 7;
        const bool isK = c < 512;
        const __nv_bfloat16* src =
            (isK ? g_kh : g_vh) + gro + (size_t)r * DV + ch * 8;
        const uint32_t dst =
            smbase + ((buf * 2 + (isK ? 0 : 1)) * TBUF + r * KSTR + ch * 8) * 2;
        asm volatile("cp.async.cg.shared.global [%0], [%1], 16;\n"
                     :: "r"(dst), "l"(src));
    }
    asm volatile("cp.async.commit_group;\n");
}

__global__ __launch_bounds__(128, 2) void attn_kernel()
{
    __shared__ __align__(16) __nv_bfloat16 sm[4 * TBUF];

    const int h  = blockIdx.y;
    const int q0 = blockIdx.x * 128;
    const int tid  = threadIdx.x;
    const int lane = tid & 31;
    const int warp = tid >> 5;             // 0..3
    const uint32_t smbase = (uint32_t)__cvta_generic_to_shared(sm);

    {
        const __nv_bfloat16* qsrc = g_qh + (size_t)q0 * DV + (size_t)h * HD;
        #pragma unroll
        for (int i = 0; i < 8; i++) {
            const int c = tid + i * 128;
            const int r = c >> 3, ch = c & 7;
            const uint4 v = *reinterpret_cast<const uint4*>(
                qsrc + (size_t)r * DV + ch * 8);
            *reinterpret_cast<uint4*>(&sm[r * KSTR + ch * 8]) = v;
        }
    }
    __syncthreads();

    uint32_t qf[2][4][4];
    {
        const int colq = (lane >> 4) * 8;
        #pragma unroll
        for (int sub = 0; sub < 2; sub++) {
            const int row = warp * 32 + sub * 16 + (lane & 15);
            #pragma unroll
            for (int ks = 0; ks < 4; ks++) {
                const uint32_t a = smbase + (row * KSTR + ks * 16 + colq) * 2;
                ldsm4(qf[sub][ks][0], qf[sub][ks][1],
                      qf[sub][ks][2], qf[sub][ks][3], a);
            }
        }
    }
    __syncthreads();

    float o[2][8][4];
    #pragma unroll
    for (int sub = 0; sub < 2; sub++)
        #pragma unroll
        for (int nd = 0; nd < 8; nd++)
            #pragma unroll
            for (int e = 0; e < 4; e++) o[sub][nd][e] = 0.f;
    float lf[2][4];
    #pragma unroll
    for (int sub = 0; sub < 2; sub++)
        #pragma unroll
        for (int e = 0; e < 4; e++) lf[sub][e] = 0.f;

    issue_kv_tile(smbase, 0, 0, h, tid);

    const int krow = (lane & 7) + 8 * (lane >> 4);
    const int kcol = 8 * ((lane >> 3) & 1);
    const int vrow = (lane & 7) + 8 * ((lane >> 3) & 1);
    const int vcol = 8 * (lane >> 4);

    for (int kt = 0; kt < 32; kt++) {
        const int b = kt & 1;
        asm volatile("cp.async.wait_group 0;\n");
        __syncthreads();
        if (kt < 31) issue_kv_tile(smbase, b ^ 1, kt + 1, h, tid);

        const uint32_t kbase = smbase + (2 * b) * TBUF * 2;
        const uint32_t vbase = smbase + (2 * b + 1) * TBUF * 2;

        float s[2][8][4];
        #pragma unroll
        for (int sub = 0; sub < 2; sub++)
            #pragma unroll
            for (int ni = 0; ni < 8; ni++)
                #pragma unroll
                for (int e = 0; e < 4; e++) s[sub][ni][e] = 0.f;

        #pragma unroll
        for (int ks = 0; ks < 4; ks++) {
            #pragma unroll
            for (int p = 0; p < 4; p++) {
                uint32_t r0, r1, r2, r3;
                const uint32_t a =
                    kbase + ((16 * p + krow) * KSTR + ks * 16 + kcol) * 2;
                ldsm4(r0, r1, r2, r3, a);
                #pragma unroll
                for (int sub = 0; sub < 2; sub++) {
                    mma_bf16(s[sub][2 * p],     qf[sub][ks], r0, r1);
                    mma_bf16(s[sub][2 * p + 1], qf[sub][ks], r2, r3);
                }
            }
        }

        #pragma unroll
        for (int kv = 0; kv < 4; kv++) {
            uint32_t pa[2][4];
            #pragma unroll
            for (int sub = 0; sub < 2; sub++) {
                pa[sub][0] = ex2_bf16x2(packbf(s[sub][2 * kv][0], s[sub][2 * kv][1]));
                pa[sub][1] = ex2_bf16x2(packbf(s[sub][2 * kv][2], s[sub][2 * kv][3]));
                pa[sub][2] = ex2_bf16x2(packbf(s[sub][2 * kv + 1][0], s[sub][2 * kv + 1][1]));
                pa[sub][3] = ex2_bf16x2(packbf(s[sub][2 * kv + 1][2], s[sub][2 * kv + 1][3]));
                mma_bf16(lf[sub], pa[sub], ONES_BF16X2, ONES_BF16X2);
            }
            #pragma unroll
            for (int p = 0; p < 4; p++) {
                uint32_t r0, r1, r2, r3;
                const uint32_t a =
                    vbase + ((16 * kv + vrow) * KSTR + 16 * p + vcol) * 2;
                ldsm4t(r0, r1, r2, r3, a);
                #pragma unroll
                for (int sub = 0; sub < 2; sub++) {
                    mma_bf16(o[sub][2 * p],     pa[sub], r0, r1);
                    mma_bf16(o[sub][2 * p + 1], pa[sub], r2, r3);
                }
            }
        }
    }

    const int g = lane >> 2;
    #pragma unroll
    for (int sub = 0; sub < 2; sub++) {
        const float inv0 = 1.f / (lf[sub][0] * 32.f);
        const float inv1 = 1.f / (lf[sub][2] * 32.f);
        const int i0 = q0 + warp * 32 + sub * 16 + g;
        const int i1 = i0 + 8;
        const int rp = h * 128 + blockIdx.x * 8 + warp * 2 + sub;
        #pragma unroll
        for (int nd = 0; nd < 8; nd++) {
            const int bc = nd * 8 + ((lane & 3) << 1);
            const int c0 = g * 64 + bc;
            const int c1 = (g + 8) * 64 + bc;
            const size_t qi0 = (size_t)i0 * DV + h * HD + bc;
            const size_t qi1 = (size_t)i1 * DV + h * HD + bc;
            const size_t o0  = (size_t)rp * DV + c0;
            const size_t o1  = (size_t)rp * DV + c1;
            const float v00 = g_q[qi0]     + o[sub][nd][0] * inv0;
            const float v01 = g_q[qi0 + 1] + o[sub][nd][1] * inv0;
            const float v10 = g_q[qi1]     + o[sub][nd][2] * inv1;
            const float v11 = g_q[qi1 + 1] + o[sub][nd][3] * inv1;
            g_attn[o0]      = v00;  g_attn[o0 + 1]  = v01;
            g_attn[o1]      = v10;  g_attn[o1 + 1]  = v11;
            g_attnh[o0]     = __float2half(v00);
            g_attnh[o0 + 1] = __float2half(v01);
            g_attnh[o1]     = __float2half(v10);
            g_attnh[o1 + 1] = __float2half(v11);
        }
    }
}

// ---------------------------------------------------------------------------
extern "C" void kernel_launch(void* const* d_in, const int* in_sizes, int n_in,
                              void* d_out, int out_size)
{
    const float* Q  = (const float*)d_in[0];
    const float* K  = (const float*)d_in[1];
    const float* bq = (const float*)d_in[3];
    const float* bk = (const float*)d_in[5];
    const float* bv = (const float*)d_in[7];
    const float* bo = (const float*)d_in[9];
    float* out = (float*)d_out;

    float *pq, *pa;
    __half *pqi, *pki, *pwq, *pwk, *pwv, *pwo, *pah;
    __nv_bfloat16 *pqh, *pkh, *pvh;
    cudaGetSymbolAddress((void**)&pq,  g_q);
    cudaGetSymbolAddress((void**)&pa,  g_attn);
    cudaGetSymbolAddress((void**)&pah, g_attnh);
    cudaGetSymbolAddress((void**)&pqi, g_qin);
    cudaGetSymbolAddress((void**)&pki, g_kin);
    cudaGetSymbolAddress((void**)&pwq, g_wqh);
    cudaGetSymbolAddress((void**)&pwk, g_wkh);
    cudaGetSymbolAddress((void**)&pwv, g_wvh);
    cudaGetSymbolAddress((void**)&pwo, g_woh);
    cudaGetSymbolAddress((void**)&pqh, g_qh);
    cudaGetSymbolAddress((void**)&pkh, g_kh);
    cudaGetSymbolAddress((void**)&pvh, g_vh);

    cudaFuncSetAttribute(gemm4, cudaFuncAttributeMaxDynamicSharedMemorySize,
                         G4SMEM);

    conv_f16<<<8192, 256>>>((const float4*)Q, (const float4*)K,
                            (const float4*)d_in[2], (const float4*)d_in[4],
                            (const float4*)d_in[6], (const float4*)d_in[8]);
    // q projection: fp32 + bf16(*log2e) outputs
    gemm4<<<dim3(16, 16), 128, G4SMEM>>>(pqi, pwq, nullptr, bq, nullptr,
                                         pq, pqh, nullptr, nullptr, 0);
    // fused k,v projection: bf16 outputs
    gemm4<<<dim3(32, 16), 128, G4SMEM>>>(pki, pwk, pwv, bk, bv,
                                         nullptr, pkh, pvh, nullptr, 1);
    attn_kernel<<<dim3(M_Q / 128, NH), 128>>>();
    // output projection with relu + residual
    gemm4<<<dim3(16, 16), 128, G4SMEM>>>(pah, pwo, nullptr, bo, nullptr,
                                         out, nullptr, nullptr, pa, 2);
}

// round 17
// speedup vs baseline: 1.0279x; 1.0279x over previous
#include <cuda_runtime.h>
#include <cuda_bf16.h>
#include <cuda_fp16.h>
#include <cstdint>

#define M_Q 2048
#define DV  1024
#define NH  16
#define HD  64
#define LOG2E 1.4426950408889634f

// Scratch (device globals: allocation-free)
__device__ float g_q[M_Q * DV];                 // fp32 q (residual for attn)
__device__ float g_attn[M_Q * DV];              // attention output (scrambled, fp32)
__device__ __half g_attnh[M_Q * DV];            // fp16 copy for Wo GEMM
__device__ __nv_bfloat16 g_qh[M_Q * DV];        // bf16 q * log2e (attention only)
__device__ __nv_bfloat16 g_kh[M_Q * DV];
__device__ __nv_bfloat16 g_vh[M_Q * DV];
// fp16 pre-converted GEMM inputs
__device__ __half g_qin[M_Q * DV];
__device__ __half g_kin[M_Q * DV];
__device__ __half g_wqh[DV * DV];
__device__ __half g_wkh[DV * DV];
__device__ __half g_wvh[DV * DV];
__device__ __half g_woh[DV * DV];

__device__ __forceinline__ void mma_f16(float (&d)[4],
                                        const uint32_t (&a)[4],
                                        uint32_t b0, uint32_t b1) {
    asm volatile(
        "mma.sync.aligned.m16n8k16.row.col.f32.f16.f16.f32 "
        "{%0,%1,%2,%3}, {%4,%5,%6,%7}, {%8,%9}, {%0,%1,%2,%3};\n"
        : "+f"(d[0]), "+f"(d[1]), "+f"(d[2]), "+f"(d[3])
        : "r"(a[0]), "r"(a[1]), "r"(a[2]), "r"(a[3]), "r"(b0), "r"(b1));
}

__device__ __forceinline__ void mma_bf16(float (&d)[4],
                                         const uint32_t (&a)[4],
                                         uint32_t b0, uint32_t b1) {
    asm volatile(
        "mma.sync.aligned.m16n8k16.row.col.f32.bf16.bf16.f32 "
        "{%0,%1,%2,%3}, {%4,%5,%6,%7}, {%8,%9}, {%0,%1,%2,%3};\n"
        : "+f"(d[0]), "+f"(d[1]), "+f"(d[2]), "+f"(d[3])
        : "r"(a[0]), "r"(a[1]), "r"(a[2]), "r"(a[3]), "r"(b0), "r"(b1));
}

__device__ __forceinline__ void ldsm4(uint32_t& r0, uint32_t& r1,
                                      uint32_t& r2, uint32_t& r3, uint32_t addr) {
    asm volatile("ldmatrix.sync.aligned.m8n8.x4.shared.b16 {%0,%1,%2,%3}, [%4];\n"
                 : "=r"(r0), "=r"(r1), "=r"(r2), "=r"(r3) : "r"(addr));
}
__device__ __forceinline__ void ldsm4t(uint32_t& r0, uint32_t& r1,
                                       uint32_t& r2, uint32_t& r3, uint32_t addr) {
    asm volatile("ldmatrix.sync.aligned.m8n8.x4.trans.shared.b16 {%0,%1,%2,%3}, [%4];\n"
                 : "=r"(r0), "=r"(r1), "=r"(r2), "=r"(r3) : "r"(addr));
}

__device__ __forceinline__ uint32_t packbf(float lo, float hi) {
    uint32_t r;
    asm("cvt.rn.bf16x2.f32 %0, %1, %2;" : "=r"(r) : "f"(hi), "f"(lo));
    return r;
}

// packed bf16x2 exp2 (sm_90+)
__device__ __forceinline__ uint32_t ex2_bf16x2(uint32_t a) {
    uint32_t r;
    asm("ex2.approx.ftz.bf16x2 %0, %1;" : "=r"(r) : "r"(a));
    return r;
}

// ---------------------------------------------------------------------------
// Pre-convert pass: fp32 -> fp16 copies of Q, K, Wq, Wk, Wv, Wo.
// ---------------------------------------------------------------------------
__global__ __launch_bounds__(256) void conv_f16(
    const float4* __restrict__ Q, const float4* __restrict__ K,
    const float4* __restrict__ Wq, const float4* __restrict__ Wk,
    const float4* __restrict__ Wv, const float4* __restrict__ Wo)
{
    const int i = blockIdx.x * 256 + threadIdx.x;   // 0 .. 2M-1
    const float4* src;
    __half* dst;
    int off;
    if (i < 524288)        { src = Q;  dst = g_qin; off = i; }
    else if (i < 1048576)  { src = K;  dst = g_kin; off = i - 524288; }
    else if (i < 1310720)  { src = Wq; dst = g_wqh; off = i - 1048576; }
    else if (i < 1572864)  { src = Wk; dst = g_wkh; off = i - 1310720; }
    else if (i < 1835008)  { src = Wv; dst = g_wvh; off = i - 1572864; }
    else                   { src = Wo; dst = g_woh; off = i - 1835008; }
    const float4 v = src[off];
    __half2* d2 = reinterpret_cast<__half2*>(dst) + off * 2;
    d2[0] = __floats2half2_rn(v.x, v.y);
    d2[1] = __floats2half2_rn(v.z, v.w);
}

// ---------------------------------------------------------------------------
// GEMM v5 (fp16): BM=128 BN=64 BK=64; 64 threads = 2 warps, warp tile 64x64.
// A-tile read 1x, B-tile read 2x through LDSM -> smem-crossbar pressure cut
// ~3x vs gemm3. 2-stage cp.async; 4 CTAs/SM (55.3KB x 4 = 221KB).
// Grids: q/out 256 blocks, kv 512 blocks -> full SM coverage.
// mode 0: Cf=fp32 + Ch0=bf16(v*log2e)   (q projection)
// mode 1: N=2048 fused; n<1024 -> W0/b0/Ch0 else W1/b1/Ch1   (k,v projection)
// mode 2: Cf = resid + relu(acc+bias)   (output projection)
// ---------------------------------------------------------------------------
#define LDH 72
#define ASTG (128 * LDH)               // A halves per stage
#define BSTG (64 * LDH)                // B halves per stage
#define STG5B ((ASTG + BSTG) * 2)      // bytes per stage
#define G5SMEM (2 * STG5B)

__device__ __forceinline__ void gemm5_issue(uint32_t smbase, int stage, int kb,
                                            const __half* __restrict__ A,
                                            const __half* __restrict__ W,
                                            int bm0, int n0, int tid)
{
    const uint32_t base = smbase + stage * STG5B;
    // A: 128 rows x 8 chunks = 1024 chunks / 64 threads = 16 per thread
    #pragma unroll
    for (int i = 0; i < 16; i++) {
        const int id = tid + i * 64;
        const int r  = id >> 3;
        const int ch = (id & 7) << 3;
        const __half* srcA = A + (size_t)(bm0 + r) * DV + kb * 64 + ch;
        asm volatile("cp.async.cg.shared.global [%0], [%1], 16;\n"
                     :: "r"(base + (r * LDH + ch) * 2), "l"(srcA));
    }
    // B: 64 rows x 8 chunks = 512 chunks / 64 threads = 8 per thread
    #pragma unroll
    for (int i = 0; i < 8; i++) {
        const int id = tid + i * 64;
        const int r  = id >> 3;
        const int ch = (id & 7) << 3;
        const __half* srcW = W + (size_t)(n0 + r) * DV + kb * 64 + ch;
        asm volatile("cp.async.cg.shared.global [%0], [%1], 16;\n"
                     :: "r"(base + (ASTG + r * LDH + ch) * 2), "l"(srcW));
    }
    asm volatile("cp.async.commit_group;\n");
}

__global__ __launch_bounds__(64, 4) void gemm5(
    const __half* __restrict__ A,
    const __half* __restrict__ W0, const __half* __restrict__ W1,
    const float* __restrict__ b0, const float* __restrict__ b1,
    float* __restrict__ Cf,
    __nv_bfloat16* __restrict__ Ch0, __nv_bfloat16* __restrict__ Ch1,
    const float* __restrict__ resid, int mode)
{
    extern __shared__ __align__(16) __half smh[];
    const uint32_t smbase = (uint32_t)__cvta_generic_to_shared(smh);

    const int tid  = threadIdx.x;
    const int lane = tid & 31;
    const int wm   = tid >> 5;         // 0..1 (m half)
    const int bm0  = blockIdx.y * 128;

    const __half* W = W0;
    const float* bias = b0;
    __nv_bfloat16* Ch = Ch0;
    int ncol0 = blockIdx.x * 64;
    if (mode == 1 && ncol0 >= DV) { W = W1; bias = b1; Ch = Ch1; ncol0 -= DV; }

    float acc[4][8][4];
    #pragma unroll
    for (int mi = 0; mi < 4; mi++)
        #pragma unroll
        for (int ni = 0; ni < 8; ni++)
            #pragma unroll
            for (int e = 0; e < 4; e++) acc[mi][ni][e] = 0.f;

    gemm5_issue(smbase, 0, 0, A, W, bm0, ncol0, tid);

    // ldmatrix lane addressing (proven patterns from gemm3)
    const int arow = lane & 15;
    const int acol = (lane >> 4) << 3;
    const int brow = (lane & 7) + 8 * (lane >> 4);
    const int bcol = ((lane >> 3) & 1) << 3;

    for (int kb = 0; kb < 16; kb++) {
        asm volatile("cp.async.wait_group 0;\n");
        __syncthreads();
        if (kb < 15) gemm5_issue(smbase, (kb + 1) & 1, kb + 1, A, W, bm0, ncol0, tid);

        const uint32_t abase = smbase + (kb & 1) * STG5B;
        const uint32_t bbase = abase + ASTG * 2;

        #pragma unroll
        for (int ks = 0; ks < 4; ks++) {
            uint32_t af[4][4];
            #pragma unroll
            for (int mi = 0; mi < 4; mi++) {
                const int r = wm * 64 + mi * 16 + arow;
                ldsm4(af[mi][0], af[mi][1], af[mi][2], af[mi][3],
                      abase + (r * LDH + ks * 16 + acol) * 2);
            }
            #pragma unroll
            for (int p = 0; p < 4; p++) {
                uint32_t r0, r1, r2, r3;
                const int n = 16 * p + brow;
                ldsm4(r0, r1, r2, r3, bbase + (n * LDH + ks * 16 + bcol) * 2);
                #pragma unroll
                for (int mi = 0; mi < 4; mi++) {
                    mma_f16(acc[mi][2 * p],     af[mi], r0, r1);
                    mma_f16(acc[mi][2 * p + 1], af[mi], r2, r3);
                }
            }
        }
        __syncthreads();
    }

    // Epilogue
    #pragma unroll
    for (int mi = 0; mi < 4; mi++) {
        #pragma unroll
        for (int ni = 0; ni < 8; ni++) {
            const int r0 = bm0 + wm * 64 + mi * 16 + (lane >> 2);
            const int c0 = ncol0 + ni * 8 + ((lane & 3) << 1);
            #pragma unroll
            for (int e = 0; e < 4; e++) {
                const int r = r0 + (e >> 1) * 8;
                const int c = c0 + (e & 1);
                float v = acc[mi][ni][e] + bias[c];
                if (mode == 2) {
                    v = resid[(size_t)r * DV + c] + fmaxf(v, 0.f);
                    Cf[(size_t)r * DV + c] = v;
                } else if (mode == 0) {
                    Cf[(size_t)r * DV + c] = v;
                    Ch[(size_t)r * DV + c] = __float2bfloat16(v * LOG2E);
                } else {
                    Ch[(size_t)r * DV + c] = __float2bfloat16(v);
                }
            }
        }
    }
}

// ---------------------------------------------------------------------------
// Attention v3 (unchanged from R14): 4 warps x 32 q-rows, bf16 MMAs,
// log2-domain scores, packed ex2, ones-MMA row sums. 128 threads, 2 CTAs/SM.
// Output scramble: O_heads[h, i, b] -> out[h*128 + (i>>4)][(i&15)*64 + b]
// ---------------------------------------------------------------------------
#define KSTR 72
#define TBUF (64 * KSTR)
#define ONES_BF16X2 0x3F803F80u

__device__ __forceinline__ void issue_kv_tile(uint32_t smbase, int buf, int kt,
                                              int h, int tid) {
    const size_t gro = (size_t)kt * 64 * DV + (size_t)h * HD;
    #pragma unroll
    for (int i = 0; i < 8; i++) {
        const int c = tid + i * 128;             // 0..1023
        const int r = (c >> 3) & 63;
        const int ch = c & 7;
        const bool isK = c < 512;
        const __nv_bfloat16* src =
            (isK ? g_kh : g_vh) + gro + (size_t)r * DV + ch * 8;
        const uint32_t dst =
            smbase + ((buf * 2 + (isK ? 0 : 1)) * TBUF + r * KSTR + ch * 8) * 2;
        asm volatile("cp.async.cg.shared.global [%0], [%1], 16;\n"
                     :: "r"(dst), "l"(src));
    }
    asm volatile("cp.async.commit_group;\n");
}

__global__ __launch_bounds__(128, 2) void attn_kernel()
{
    __shared__ __align__(16) __nv_bfloat16 sm[4 * TBUF];

    const int h  = blockIdx.y;
    const int q0 = blockIdx.x * 128;
    const int tid  = threadIdx.x;
    const int lane = tid & 31;
    const int warp = tid >> 5;             // 0..3
    const uint32_t smbase = (uint32_t)__cvta_generic_to_shared(sm);

    {
        const __nv_bfloat16* qsrc = g_qh + (size_t)q0 * DV + (size_t)h * HD;
        #pragma unroll
        for (int i = 0; i < 8; i++) {
            const int c = tid + i * 128;
            const int r = c >> 3, ch = c & 7;
            const uint4 v = *reinterpret_cast<const uint4*>(
                qsrc + (size_t)r * DV + ch * 8);
            *reinterpret_cast<uint4*>(&sm[r * KSTR + ch * 8]) = v;
        }
    }
    __syncthreads();

    uint32_t qf[2][4][4];
    {
        const int colq = (lane >> 4) * 8;
        #pragma unroll
        for (int sub = 0; sub < 2; sub++) {
            const int row = warp * 32 + sub * 16 + (lane & 15);
            #pragma unroll
            for (int ks = 0; ks < 4; ks++) {
                const uint32_t a = smbase + (row * KSTR + ks * 16 + colq) * 2;
                ldsm4(qf[sub][ks][0], qf[sub][ks][1],
                      qf[sub][ks][2], qf[sub][ks][3], a);
            }
        }
    }
    __syncthreads();

    float o[2][8][4];
    #pragma unroll
    for (int sub = 0; sub < 2; sub++)
        #pragma unroll
        for (int nd = 0; nd < 8; nd++)
            #pragma unroll
            for (int e = 0; e < 4; e++) o[sub][nd][e] = 0.f;
    float lf[2][4];
    #pragma unroll
    for (int sub = 0; sub < 2; sub++)
        #pragma unroll
        for (int e = 0; e < 4; e++) lf[sub][e] = 0.f;

    issue_kv_tile(smbase, 0, 0, h, tid);

    const int krow = (lane & 7) + 8 * (lane >> 4);
    const int kcol = 8 * ((lane >> 3) & 1);
    const int vrow = (lane & 7) + 8 * ((lane >> 3) & 1);
    const int vcol = 8 * (lane >> 4);

    for (int kt = 0; kt < 32; kt++) {
        const int b = kt & 1;
        asm volatile("cp.async.wait_group 0;\n");
        __syncthreads();
        if (kt < 31) issue_kv_tile(smbase, b ^ 1, kt + 1, h, tid);

        const uint32_t kbase = smbase + (2 * b) * TBUF * 2;
        const uint32_t vbase = smbase + (2 * b + 1) * TBUF * 2;

        float s[2][8][4];
        #pragma unroll
        for (int sub = 0; sub < 2; sub++)
            #pragma unroll
            for (int ni = 0; ni < 8; ni++)
                #pragma unroll
                for (int e = 0; e < 4; e++) s[sub][ni][e] = 0.f;

        #pragma unroll
        for (int ks = 0; ks < 4; ks++) {
            #pragma unroll
            for (int p = 0; p < 4; p++) {
                uint32_t r0, r1, r2, r3;
                const uint32_t a =
                    kbase + ((16 * p + krow) * KSTR + ks * 16 + kcol) * 2;
                ldsm4(r0, r1, r2, r3, a);
                #pragma unroll
                for (int sub = 0; sub < 2; sub++) {
                    mma_bf16(s[sub][2 * p],     qf[sub][ks], r0, r1);
                    mma_bf16(s[sub][2 * p + 1], qf[sub][ks], r2, r3);
                }
            }
        }

        #pragma unroll
        for (int kv = 0; kv < 4; kv++) {
            uint32_t pa[2][4];
            #pragma unroll
            for (int sub = 0; sub < 2; sub++) {
                pa[sub][0] = ex2_bf16x2(packbf(s[sub][2 * kv][0], s[sub][2 * kv][1]));
                pa[sub][1] = ex2_bf16x2(packbf(s[sub][2 * kv][2], s[sub][2 * kv][3]));
                pa[sub][2] = ex2_bf16x2(packbf(s[sub][2 * kv + 1][0], s[sub][2 * kv + 1][1]));
                pa[sub][3] = ex2_bf16x2(packbf(s[sub][2 * kv + 1][2], s[sub][2 * kv + 1][3]));
                mma_bf16(lf[sub], pa[sub], ONES_BF16X2, ONES_BF16X2);
            }
            #pragma unroll
            for (int p = 0; p < 4; p++) {
                uint32_t r0, r1, r2, r3;
                const uint32_t a =
                    vbase + ((16 * kv + vrow) * KSTR + 16 * p + vcol) * 2;
                ldsm4t(r0, r1, r2, r3, a);
                #pragma unroll
                for (int sub = 0; sub < 2; sub++) {
                    mma_bf16(o[sub][2 * p],     pa[sub], r0, r1);
                    mma_bf16(o[sub][2 * p + 1], pa[sub], r2, r3);
                }
            }
        }
    }

    const int g = lane >> 2;
    #pragma unroll
    for (int sub = 0; sub < 2; sub++) {
        const float inv0 = 1.f / (lf[sub][0] * 32.f);
        const float inv1 = 1.f / (lf[sub][2] * 32.f);
        const int i0 = q0 + warp * 32 + sub * 16 + g;
        const int i1 = i0 + 8;
        const int rp = h * 128 + blockIdx.x * 8 + warp * 2 + sub;
        #pragma unroll
        for (int nd = 0; nd < 8; nd++) {
            const int bc = nd * 8 + ((lane & 3) << 1);
            const int c0 = g * 64 + bc;
            const int c1 = (g + 8) * 64 + bc;
            const size_t qi0 = (size_t)i0 * DV + h * HD + bc;
            const size_t qi1 = (size_t)i1 * DV + h * HD + bc;
            const size_t o0  = (size_t)rp * DV + c0;
            const size_t o1  = (size_t)rp * DV + c1;
            const float v00 = g_q[qi0]     + o[sub][nd][0] * inv0;
            const float v01 = g_q[qi0 + 1] + o[sub][nd][1] * inv0;
            const float v10 = g_q[qi1]     + o[sub][nd][2] * inv1;
            const float v11 = g_q[qi1 + 1] + o[sub][nd][3] * inv1;
            g_attn[o0]      = v00;  g_attn[o0 + 1]  = v01;
            g_attn[o1]      = v10;  g_attn[o1 + 1]  = v11;
            g_attnh[o0]     = __float2half(v00);
            g_attnh[o0 + 1] = __float2half(v01);
            g_attnh[o1]     = __float2half(v10);
            g_attnh[o1 + 1] = __float2half(v11);
        }
    }
}

// ---------------------------------------------------------------------------
extern "C" void kernel_launch(void* const* d_in, const int* in_sizes, int n_in,
                              void* d_out, int out_size)
{
    const float* Q  = (const float*)d_in[0];
    const float* K  = (const float*)d_in[1];
    const float* bq = (const float*)d_in[3];
    const float* bk = (const float*)d_in[5];
    const float* bv = (const float*)d_in[7];
    const float* bo = (const float*)d_in[9];
    float* out = (float*)d_out;

    float *pq, *pa;
    __half *pqi, *pki, *pwq, *pwk, *pwv, *pwo, *pah;
    __nv_bfloat16 *pqh, *pkh, *pvh;
    cudaGetSymbolAddress((void**)&pq,  g_q);
    cudaGetSymbolAddress((void**)&pa,  g_attn);
    cudaGetSymbolAddress((void**)&pah, g_attnh);
    cudaGetSymbolAddress((void**)&pqi, g_qin);
    cudaGetSymbolAddress((void**)&pki, g_kin);
    cudaGetSymbolAddress((void**)&pwq, g_wqh);
    cudaGetSymbolAddress((void**)&pwk, g_wkh);
    cudaGetSymbolAddress((void**)&pwv, g_wvh);
    cudaGetSymbolAddress((void**)&pwo, g_woh);
    cudaGetSymbolAddress((void**)&pqh, g_qh);
    cudaGetSymbolAddress((void**)&pkh, g_kh);
    cudaGetSymbolAddress((void**)&pvh, g_vh);

    cudaFuncSetAttribute(gemm5, cudaFuncAttributeMaxDynamicSharedMemorySize,
                         G5SMEM);

    conv_f16<<<8192, 256>>>((const float4*)Q, (const float4*)K,
                            (const float4*)d_in[2], (const float4*)d_in[4],
                            (const float4*)d_in[6], (const float4*)d_in[8]);
    // q projection: fp32 + bf16(*log2e) outputs
    gemm5<<<dim3(16, 16), 64, G5SMEM>>>(pqi, pwq, nullptr, bq, nullptr,
                                        pq, pqh, nullptr, nullptr, 0);
    // fused k,v projection: bf16 outputs
    gemm5<<<dim3(32, 16), 64, G5SMEM>>>(pki, pwk, pwv, bk, bv,
                                        nullptr, pkh, pvh, nullptr, 1);
    attn_kernel<<<dim3(M_Q / 128, NH), 128>>>();
    // output projection with relu + residual
    gemm5<<<dim3(16, 16), 64, G5SMEM>>>(pah, pwo, nullptr, bo, nullptr,
                                        out, nullptr, nullptr, pa, 2);
}